// round 5
// baseline (speedup 1.0000x reference)
#include <cuda_runtime.h>

#define IMG_H 512
#define IMG_W 512
#define TILE_H 32
#define NTHREADS 128   // 128 threads x float4 = 512 cols = one full row

__device__ __forceinline__ int reflr(int g) {
    // reflect-101: -1 -> 1, -2 -> 2, 512 -> 510, 513 -> 509
    g = g < 0 ? -g : g;
    if (g >= IMG_H) g = 2 * IMG_H - 2 - g;
    return g;
}

// Horizontal 5-tap sums for cols c..c+3 from A=[c-4..c-1], B=[c..c+3], C=[c+4..c+7].
// Edge threads (isL: c==0, isR: c==508) use reflect-101 overrides and never
// dereference A/C respectively.
__device__ __forceinline__ float4 hsum(float4 A, float4 B, float4 C, bool isL, bool isR)
{
    float s = B.x + B.y + B.z;          // shared middle
    float t = B.w + C.x;
    float4 h;
    h.x = A.z + A.w + s;                // v[c-2..c+2]
    h.y = A.w + s + B.w;                // v[c-1..c+3]
    h.z = s + t;                        // v[c..c+4]
    h.w = B.y + B.z + t + C.y;          // v[c+1..c+5]
    if (isL) {                          // cols -2,-1 -> 2,1
        h.x = s + B.y + B.z;            // 2*Bz + 2*By + Bx
        h.y = s + B.y + B.w;
    }
    if (isR) {                          // cols 512,513 -> 510,509
        h.z = s + B.w + B.z;
        h.w = B.y + B.z + B.w + B.z + B.y;
    }
    return h;
}

__device__ __forceinline__ float4 ld4(const float* p) {
    return *reinterpret_cast<const float4*>(p);
}

__global__ __launch_bounds__(NTHREADS, 10)
void smooth5_kernel(const float* __restrict__ in, float* __restrict__ out)
{
    const int tid   = threadIdx.x;
    const int c0    = tid * 4;
    const int plane = blockIdx.y;
    const int row0  = blockIdx.x * TILE_H;

    const float* ip = in  + (size_t)plane * (IMG_H * IMG_W);
    float*       op = out + (size_t)plane * (IMG_H * IMG_W);

    const bool isL = (c0 == 0);
    const bool isR = (c0 == IMG_W - 4);

    float4 Z = make_float4(0.f, 0.f, 0.f, 0.f);

    // ---- warm-up: hsums of source rows row0-2 .. row0+1 (reflect at top) ----
    float4 h0, h1, h2, h3;
    {
        const float* r;
        float4 A, B, C;
        r = ip + (size_t)reflr(row0 - 2) * IMG_W;
        A = isL ? Z : ld4(r + c0 - 4); B = ld4(r + c0); C = isR ? Z : ld4(r + c0 + 4);
        h0 = hsum(A, B, C, isL, isR);
        r = ip + (size_t)reflr(row0 - 1) * IMG_W;
        A = isL ? Z : ld4(r + c0 - 4); B = ld4(r + c0); C = isR ? Z : ld4(r + c0 + 4);
        h1 = hsum(A, B, C, isL, isR);
        r = ip + (size_t)(row0) * IMG_W;
        A = isL ? Z : ld4(r + c0 - 4); B = ld4(r + c0); C = isR ? Z : ld4(r + c0 + 4);
        h2 = hsum(A, B, C, isL, isR);
        r = ip + (size_t)(row0 + 1) * IMG_W;
        A = isL ? Z : ld4(r + c0 - 4); B = ld4(r + c0); C = isR ? Z : ld4(r + c0 + 4);
        h3 = hsum(A, B, C, isL, isR);
    }

    const float inv25 = 1.0f / 25.0f;

    if (row0 + TILE_H + 2 <= IMG_H) {
        // ---------- interior fast path (all blocks except the last row-tile) ----------
        const float* sp = ip + (size_t)(row0 + 2) * IMG_W + c0;
        float*       dp = op + (size_t)(row0)     * IMG_W + c0;
        #pragma unroll 4
        for (int r = 0; r < TILE_H; ++r) {
            float4 A = isL ? Z : ld4(sp - 4);
            float4 B = ld4(sp);
            float4 C = isR ? Z : ld4(sp + 4);
            sp += IMG_W;
            float4 h = hsum(A, B, C, isL, isR);
            float4 o;
            o.x = (h0.x + h1.x + h2.x + h3.x + h.x) * inv25;
            o.y = (h0.y + h1.y + h2.y + h3.y + h.y) * inv25;
            o.z = (h0.z + h1.z + h2.z + h3.z + h.z) * inv25;
            o.w = (h0.w + h1.w + h2.w + h3.w + h.w) * inv25;
            __stcs(reinterpret_cast<float4*>(dp), o);
            dp += IMG_W;
            h0 = h1; h1 = h2; h2 = h3; h3 = h;
        }
    } else {
        // ---------- bottom tile: reflected row indexing ----------
        #pragma unroll 4
        for (int r = 0; r < TILE_H; ++r) {
            const float* rp = ip + (size_t)reflr(row0 + 2 + r) * IMG_W;
            float4 A = isL ? Z : ld4(rp + c0 - 4);
            float4 B = ld4(rp + c0);
            float4 C = isR ? Z : ld4(rp + c0 + 4);
            float4 h = hsum(A, B, C, isL, isR);
            float4 o;
            o.x = (h0.x + h1.x + h2.x + h3.x + h.x) * inv25;
            o.y = (h0.y + h1.y + h2.y + h3.y + h.y) * inv25;
            o.z = (h0.z + h1.z + h2.z + h3.z + h.z) * inv25;
            o.w = (h0.w + h1.w + h2.w + h3.w + h.w) * inv25;
            __stcs(reinterpret_cast<float4*>(op + (size_t)(row0 + r) * IMG_W + c0), o);
            h0 = h1; h1 = h2; h2 = h3; h3 = h;
        }
    }
}

extern "C" void kernel_launch(void* const* d_in, const int* in_sizes, int n_in,
                              void* d_out, int out_size)
{
    const float* in  = (const float*)d_in[0];
    float*       out = (float*)d_out;
    int planes = in_sizes[0] / (IMG_H * IMG_W);   // B*C = 96
    dim3 grid(IMG_H / TILE_H, planes);
    smooth5_kernel<<<grid, NTHREADS>>>(in, out);
}

// round 6
// speedup vs baseline: 1.1443x; 1.1443x over previous
#include <cuda_runtime.h>

#define IMG_H 512
#define IMG_W 512
#define TILE_H 16
#define NTHREADS 256   // thread owns cols 2t, 2t+1

__device__ __forceinline__ int reflr(int g) {
    // reflect-101: -1 -> 1, -2 -> 2, 512 -> 510, 513 -> 509
    g = g < 0 ? -g : g;
    if (g >= IMG_H) g = 2 * IMG_H - 2 - g;
    return g;
}

__device__ __forceinline__ float2 ld2(const float* p) {
    return *reinterpret_cast<const float2*>(p);
}

// Horizontal 5-tap sums for cols c,c+1 from A=(c-2,c-1), B=(c,c+1), C=(c+2,c+3).
// Edge lanes patch A/C by register rename (reflect-101 identity):
//   t=0:   A=(C.x,B.y)   [cols -2,-1 -> 2,1]
//   t=255: C=(B.x,A.y)   [cols 512,513 -> 510,509]
__device__ __forceinline__ float2 hrow(const float* __restrict__ rp, int c0,
                                       bool isL, bool isR)
{
    float2 Z = make_float2(0.f, 0.f);
    float2 A = isL ? Z : ld2(rp + c0 - 2);
    float2 B = ld2(rp + c0);
    float2 C = isR ? Z : ld2(rp + c0 + 2);
    if (isL) { A.x = C.x; A.y = B.y; }
    if (isR) { C.x = B.x; C.y = A.y; }
    float u = A.y + B.x + B.y + C.x;
    return make_float2(u + A.x, u + C.y);
}

__global__ __launch_bounds__(NTHREADS, 7)
void smooth5_kernel(const float* __restrict__ in, float* __restrict__ out)
{
    const int tid   = threadIdx.x;
    const int c0    = 2 * tid;
    const int plane = blockIdx.y;
    const int row0  = blockIdx.x * TILE_H;

    const float* ip = in  + (size_t)plane * (IMG_H * IMG_W);
    float*       op = out + (size_t)plane * (IMG_H * IMG_W);

    const bool isL = (tid == 0);
    const bool isR = (tid == NTHREADS - 1);

    // Warm-up: horizontal sums of source rows row0-2 .. row0+1 (top reflected)
    float2 h0 = hrow(ip + (size_t)reflr(row0 - 2) * IMG_W, c0, isL, isR);
    float2 h1 = hrow(ip + (size_t)reflr(row0 - 1) * IMG_W, c0, isL, isR);
    float2 h2 = hrow(ip + (size_t)(row0)          * IMG_W, c0, isL, isR);
    float2 h3 = hrow(ip + (size_t)(row0 + 1)      * IMG_W, c0, isL, isR);

    const float inv25 = 1.0f / 25.0f;

    if (row0 + TILE_H + 2 <= IMG_H) {
        // ---------- interior fast path ----------
        const float* sp = ip + (size_t)(row0 + 2) * IMG_W;
        float*       dp = op + (size_t)(row0)     * IMG_W;
        #pragma unroll
        for (int r = 0; r < TILE_H; ++r) {
            float2 h = hrow(sp, c0, isL, isR);
            sp += IMG_W;
            float2 o;
            o.x = (h0.x + h1.x + h2.x + h3.x + h.x) * inv25;
            o.y = (h0.y + h1.y + h2.y + h3.y + h.y) * inv25;
            *reinterpret_cast<float2*>(dp + c0) = o;
            dp += IMG_W;
            h0 = h1; h1 = h2; h2 = h3; h3 = h;
        }
    } else {
        // ---------- bottom tile: reflected row indexing ----------
        #pragma unroll
        for (int r = 0; r < TILE_H; ++r) {
            const float* rp = ip + (size_t)reflr(row0 + 2 + r) * IMG_W;
            float2 h = hrow(rp, c0, isL, isR);
            float2 o;
            o.x = (h0.x + h1.x + h2.x + h3.x + h.x) * inv25;
            o.y = (h0.y + h1.y + h2.y + h3.y + h.y) * inv25;
            *reinterpret_cast<float2*>(op + (size_t)(row0 + r) * IMG_W + c0) = o;
            h0 = h1; h1 = h2; h2 = h3; h3 = h;
        }
    }
}

extern "C" void kernel_launch(void* const* d_in, const int* in_sizes, int n_in,
                              void* d_out, int out_size)
{
    const float* in  = (const float*)d_in[0];
    float*       out = (float*)d_out;
    int planes = in_sizes[0] / (IMG_H * IMG_W);   // B*C = 96
    dim3 grid(IMG_H / TILE_H, planes);
    smooth5_kernel<<<grid, NTHREADS>>>(in, out);
}

// round 7
// speedup vs baseline: 1.1755x; 1.0272x over previous
#include <cuda_runtime.h>

#define IMG_H 512
#define IMG_W 512
#define TILE_H 16
#define NTHREADS 256   // thread owns cols 2t, 2t+1

__device__ __forceinline__ int reflr(int g) {
    // reflect-101: -1 -> 1, -2 -> 2, 512 -> 510, 513 -> 509
    g = g < 0 ? -g : g;
    if (g >= IMG_H) g = 2 * IMG_H - 2 - g;
    return g;
}

__device__ __forceinline__ float2 ld2(const float* p) {
    return *reinterpret_cast<const float2*>(p);
}

// Load the 3 float2's needed for cols c,c+1 of one source row.
__device__ __forceinline__ void ldrow(const float* __restrict__ rp, int c0,
                                      bool isL, bool isR,
                                      float2& A, float2& B, float2& C)
{
    A = isL ? make_float2(0.f, 0.f) : ld2(rp + c0 - 2);
    B = ld2(rp + c0);
    C = isR ? make_float2(0.f, 0.f) : ld2(rp + c0 + 2);
}

// Horizontal 5-tap sums from A=(c-2,c-1), B=(c,c+1), C=(c+2,c+3).
// Edge lanes patch by register rename (reflect-101 identity):
//   t=0:   A=(C.x,B.y)   [cols -2,-1 -> 2,1]
//   t=255: C=(B.x,A.y)   [cols 512,513 -> 510,509]
__device__ __forceinline__ float2 hsum2(float2 A, float2 B, float2 C,
                                        bool isL, bool isR)
{
    if (isL) { A.x = C.x; A.y = B.y; }
    if (isR) { C.x = B.x; C.y = A.y; }
    float u = A.y + B.x + B.y + C.x;
    return make_float2(u + A.x, u + C.y);
}

__global__ __launch_bounds__(NTHREADS, 6)
void smooth5_kernel(const float* __restrict__ in, float* __restrict__ out)
{
    const int tid   = threadIdx.x;
    const int c0    = 2 * tid;
    const int plane = blockIdx.y;
    const int row0  = blockIdx.x * TILE_H;

    const float* ip = in  + (size_t)plane * (IMG_H * IMG_W);
    float*       op = out + (size_t)plane * (IMG_H * IMG_W);

    const bool isL = (tid == 0);
    const bool isR = (tid == NTHREADS - 1);

    // Warm-up: horizontal sums of source rows row0-2 .. row0+1 (top reflected)
    float2 A, B, C;
    ldrow(ip + (size_t)reflr(row0 - 2) * IMG_W, c0, isL, isR, A, B, C);
    float2 h0 = hsum2(A, B, C, isL, isR);
    ldrow(ip + (size_t)reflr(row0 - 1) * IMG_W, c0, isL, isR, A, B, C);
    float2 h1 = hsum2(A, B, C, isL, isR);
    ldrow(ip + (size_t)(row0) * IMG_W, c0, isL, isR, A, B, C);
    float2 h2 = hsum2(A, B, C, isL, isR);
    ldrow(ip + (size_t)(row0 + 1) * IMG_W, c0, isL, isR, A, B, C);
    float2 h3 = hsum2(A, B, C, isL, isR);

    const float inv25 = 1.0f / 25.0f;

    if (row0 + TILE_H + 2 <= IMG_H) {
        // ---------- interior fast path, 1-row software pipeline ----------
        const float* sp = ip + (size_t)(row0 + 2) * IMG_W;
        float*       dp = op + (size_t)(row0)     * IMG_W + c0;

        float2 cA, cB, cC;                       // row r+2 inputs (current)
        ldrow(sp, c0, isL, isR, cA, cB, cC);
        sp += IMG_W;

        #pragma unroll
        for (int r = 0; r < TILE_H; ++r) {
            float2 nA, nB, nC;                   // prefetch row r+3 inputs
            if (r < TILE_H - 1) {
                ldrow(sp, c0, isL, isR, nA, nB, nC);
                sp += IMG_W;
            }
            float2 h = hsum2(cA, cB, cC, isL, isR);
            float2 o;
            o.x = (h0.x + h1.x + h2.x + h3.x + h.x) * inv25;
            o.y = (h0.y + h1.y + h2.y + h3.y + h.y) * inv25;
            __stcs(reinterpret_cast<float2*>(dp), o);   // streaming: don't pollute L2
            dp += IMG_W;
            h0 = h1; h1 = h2; h2 = h3; h3 = h;
            cA = nA; cB = nB; cC = nC;
        }
    } else {
        // ---------- bottom tile: reflected row indexing ----------
        #pragma unroll
        for (int r = 0; r < TILE_H; ++r) {
            const float* rp = ip + (size_t)reflr(row0 + 2 + r) * IMG_W;
            float2 a, b, c;
            ldrow(rp, c0, isL, isR, a, b, c);
            float2 h = hsum2(a, b, c, isL, isR);
            float2 o;
            o.x = (h0.x + h1.x + h2.x + h3.x + h.x) * inv25;
            o.y = (h0.y + h1.y + h2.y + h3.y + h.y) * inv25;
            __stcs(reinterpret_cast<float2*>(op + (size_t)(row0 + r) * IMG_W + c0), o);
            h0 = h1; h1 = h2; h2 = h3; h3 = h;
        }
    }
}

extern "C" void kernel_launch(void* const* d_in, const int* in_sizes, int n_in,
                              void* d_out, int out_size)
{
    const float* in  = (const float*)d_in[0];
    float*       out = (float*)d_out;
    int planes = in_sizes[0] / (IMG_H * IMG_W);   // B*C = 96
    dim3 grid(IMG_H / TILE_H, planes);
    smooth5_kernel<<<grid, NTHREADS>>>(in, out);
}